// round 13
// baseline (speedup 1.0000x reference)
#include <cuda_runtime.h>
#include <cuda_fp16.h>
#include <math.h>
#include <stdint.h>
#include <stddef.h>

// Problem dims (fixed)
#define S_   2048
#define D_   2048
#define NH   16
#define DH   128
#define QKV3 6144
#define DFF  8192

// ===================== low-level helpers (sm_100 baseline ISA) ==============
__device__ __forceinline__ uint32_t smem_to_u32(const void* p) {
    uint32_t a;
    asm("{ .reg .u64 t; cvta.to.shared.u64 t, %1; cvt.u32.u64 %0, t; }"
        : "=r"(a) : "l"(p));
    return a;
}
__device__ __forceinline__ void cpa16(uint32_t dst, const void* src) {
    asm volatile("cp.async.cg.shared.global [%0], [%1], 16;" :: "r"(dst), "l"(src));
}
__device__ __forceinline__ void ldsm_x4(uint32_t& r0, uint32_t& r1,
                                        uint32_t& r2, uint32_t& r3, uint32_t addr) {
    asm volatile("ldmatrix.sync.aligned.m8n8.x4.shared.b16 {%0,%1,%2,%3}, [%4];"
                 : "=r"(r0), "=r"(r1), "=r"(r2), "=r"(r3) : "r"(addr));
}
__device__ __forceinline__ void ldsm_x2(uint32_t& r0, uint32_t& r1, uint32_t addr) {
    asm volatile("ldmatrix.sync.aligned.m8n8.x2.shared.b16 {%0,%1}, [%2];"
                 : "=r"(r0), "=r"(r1) : "r"(addr));
}
__device__ __forceinline__ void mma_f16(float* c, const uint32_t* a, const uint32_t* b) {
    asm volatile("mma.sync.aligned.m16n8k16.row.col.f32.f16.f16.f32 "
                 "{%0,%1,%2,%3},{%4,%5,%6,%7},{%8,%9},{%0,%1,%2,%3};"
                 : "+f"(c[0]), "+f"(c[1]), "+f"(c[2]), "+f"(c[3])
                 : "r"(a[0]), "r"(a[1]), "r"(a[2]), "r"(a[3]), "r"(b[0]), "r"(b[1]));
}

// ===================== scratch (device globals) =============================
// g_scores: 4x fp32 P@V partial buffers (scores themselves live in g_p).
__device__ __align__(128) float g_scores[(size_t)4 * S_ * D_ + 128];
__device__ __align__(128) float g_tmp[(size_t)S_ * D_];
__device__ __align__(128) float g_x1[(size_t)S_ * D_];

__device__ __align__(128) __half g_h[(size_t)S_ * D_];
__device__ __align__(128) __half g_qkv[(size_t)S_ * QKV3];
__device__ __align__(128) __half g_p[(size_t)NH * S_ * S_];      // scores then p
__device__ __align__(128) __half g_vt[(size_t)NH * DH * S_];
__device__ __align__(128) __half g_ctx[(size_t)S_ * D_];
__device__ __align__(128) __half g_m1[(size_t)S_ * DFF];

__device__ __align__(128) __half g_wq[(size_t)QKV3 * D_];
__device__ __align__(128) __half g_wo[(size_t)D_ * D_];
__device__ __align__(128) __half g_w1[(size_t)DFF * D_];
__device__ __align__(128) __half g_w2[(size_t)D_ * DFF];

// ===================== reductions ===========================================
__device__ __forceinline__ float blockReduceSum(float v) {
    __shared__ float red[32];
    __syncthreads();
    int lane = threadIdx.x & 31, w = threadIdx.x >> 5;
    #pragma unroll
    for (int o = 16; o; o >>= 1) v += __shfl_xor_sync(0xffffffffu, v, o);
    if (lane == 0) red[w] = v;
    __syncthreads();
    if (w == 0) {
        float r = (lane < ((blockDim.x + 31) >> 5)) ? red[lane] : 0.f;
        #pragma unroll
        for (int o = 16; o; o >>= 1) r += __shfl_xor_sync(0xffffffffu, r, o);
        if (lane == 0) red[0] = r;
    }
    __syncthreads();
    return red[0];
}
__device__ __forceinline__ float blockReduceMax(float v) {
    __shared__ float red[32];
    __syncthreads();
    int lane = threadIdx.x & 31, w = threadIdx.x >> 5;
    #pragma unroll
    for (int o = 16; o; o >>= 1) v = fmaxf(v, __shfl_xor_sync(0xffffffffu, v, o));
    if (lane == 0) red[w] = v;
    __syncthreads();
    if (w == 0) {
        float r = (lane < ((blockDim.x + 31) >> 5)) ? red[lane] : -3.0e38f;
        #pragma unroll
        for (int o = 16; o; o >>= 1) r = fmaxf(r, __shfl_xor_sync(0xffffffffu, r, o));
        if (lane == 0) red[0] = r;
    }
    __syncthreads();
    return red[0];
}

// ===================== LayerNorm ============================================
template<bool TOF16>
__global__ void __launch_bounds__(256) ln_kernel(
    const float* __restrict__ in, const float* __restrict__ gam,
    const float* __restrict__ bet, const float* __restrict__ res,
    float* __restrict__ outf, __half* __restrict__ oh)
{
    const int row = blockIdx.x;
    const float* x = in + (size_t)row * D_;
    __shared__ float sm[D_];
    float s = 0.f;
    for (int j = threadIdx.x; j < D_; j += blockDim.x) {
        float v = x[j]; sm[j] = v; s += v;
    }
    const float mu = blockReduceSum(s) * (1.0f / D_);
    float sq = 0.f;
    for (int j = threadIdx.x; j < D_; j += blockDim.x) {
        float d = sm[j] - mu; sq += d * d;
    }
    const float var = blockReduceSum(sq) * (1.0f / D_);
    const float inv = rsqrtf(var + 1e-5f);
    for (int j = threadIdx.x; j < D_; j += blockDim.x) {
        float v = (sm[j] - mu) * inv * gam[j] + bet[j];
        if (TOF16) {
            oh[(size_t)row * D_ + j] = __float2half_rn(v);
        } else {
            if (res) v += res[(size_t)row * D_ + j];
            outf[(size_t)row * D_ + j] = v;
        }
    }
}

// ===================== fused: x1 = x + LN(a), ho = LN(x1) -> fp16 ==========
__global__ void __launch_bounds__(256) ln_res_ln_kernel(
    const float* __restrict__ a, const float* __restrict__ g1,
    const float* __restrict__ b1, const float* __restrict__ x,
    const float* __restrict__ g2, const float* __restrict__ b2,
    float* __restrict__ x1_out, __half* __restrict__ ho)
{
    const int row = blockIdx.x;
    const float* ar = a + (size_t)row * D_;
    __shared__ float sm[D_];
    float s = 0.f;
    for (int j = threadIdx.x; j < D_; j += blockDim.x) {
        float v = ar[j]; sm[j] = v; s += v;
    }
    float mu = blockReduceSum(s) * (1.0f / D_);
    float sq = 0.f;
    for (int j = threadIdx.x; j < D_; j += blockDim.x) {
        float d = sm[j] - mu; sq += d * d;
    }
    float var = blockReduceSum(sq) * (1.0f / D_);
    float inv = rsqrtf(var + 1e-5f);
    float s2 = 0.f;
    for (int j = threadIdx.x; j < D_; j += blockDim.x) {
        float v = (sm[j] - mu) * inv * g1[j] + b1[j] + x[(size_t)row * D_ + j];
        sm[j] = v;
        x1_out[(size_t)row * D_ + j] = v;
        s2 += v;
    }
    mu = blockReduceSum(s2) * (1.0f / D_);
    sq = 0.f;
    for (int j = threadIdx.x; j < D_; j += blockDim.x) {
        float d = sm[j] - mu; sq += d * d;
    }
    var = blockReduceSum(sq) * (1.0f / D_);
    inv = rsqrtf(var + 1e-5f);
    for (int j = threadIdx.x; j < D_; j += blockDim.x)
        ho[(size_t)row * D_ + j] =
            __float2half_rn((sm[j] - mu) * inv * g2[j] + b2[j]);
}

// ===================== causal softmax (in place, fp16) ======================
// h0: first head of this launch's range (gridDim.y heads processed).
__global__ void __launch_bounds__(256) softmax_kernel(int h0)
{
    const int i = blockIdx.x;
    const int h = blockIdx.y + h0;
    const size_t base = ((size_t)h * S_ + i) * S_;
    __half* ph = g_p + base;
    const int n = i + 1;
    const int fill_end = ((i >> 7) + 1) << 7;   // next multiple of 128
    __shared__ float sm[S_];
    float m = -3.0e38f;
    for (int j = threadIdx.x; j < n; j += blockDim.x) {
        float v = __half2float(ph[j]); sm[j] = v; m = fmaxf(m, v);
    }
    m = blockReduceMax(m);
    float s = 0.f;
    for (int j = threadIdx.x; j < n; j += blockDim.x) {
        float e = expf(sm[j] - m); sm[j] = e; s += e;
    }
    const float inv = 1.0f / blockReduceSum(s);
    const __half z = __float2half_rn(0.f);
    for (int j = threadIdx.x; j < n; j += blockDim.x)
        ph[j] = __float2half_rn(sm[j] * inv);
    for (int j = n + threadIdx.x; j < fill_end; j += blockDim.x) ph[j] = z;
}

// ===================== weight convert + transpose ===========================
__global__ void __launch_bounds__(256) convw_kernel(
    const float* __restrict__ W, int K, int N, __half* __restrict__ o)
{
    __shared__ float t[64][33];
    const int n0 = blockIdx.x * 32, k0 = blockIdx.y * 64;
    const int tx = threadIdx.x, ty = threadIdx.y;  // 32 x 8
    #pragma unroll
    for (int j = 0; j < 8; j++)
        t[ty + j * 8][tx] = W[(size_t)(k0 + ty + j * 8) * N + n0 + tx];
    __syncthreads();
    #pragma unroll
    for (int j = 0; j < 4; j++) {
        const int n = ty + j * 8;
        __half2 hv = __floats2half2_rn(t[tx * 2][n], t[tx * 2 + 1][n]);
        *(__half2*)(o + (size_t)(n0 + n) * K + k0 + tx * 2) = hv;
    }
}

// ===================== V transpose (fp16) ===================================
__global__ void __launch_bounds__(256) vtrans_kernel()
{
    __shared__ __half th[32][33];
    const int h = blockIdx.z;
    const int s0 = blockIdx.x * 32, d0 = blockIdx.y * 32;
    const int tx = threadIdx.x, ty = threadIdx.y;
    #pragma unroll
    for (int j = 0; j < 4; j++)
        th[ty + j * 8][tx] =
            g_qkv[(size_t)(s0 + ty + j * 8) * QKV3 + 2 * D_ + h * DH + d0 + tx];
    __syncthreads();
    #pragma unroll
    for (int j = 0; j < 4; j++)
        g_vt[((size_t)h * DH + d0 + ty + j * 8) * S_ + s0 + tx] = th[tx][ty + j * 8];
}

// ===================== P@V partial combine ==================================
__global__ void __launch_bounds__(256) combine_pv_kernel()
{
    const size_t idx = ((size_t)blockIdx.x * 256 + threadIdx.x) * 4;
    const int r = (int)(idx >> 11);          // row = idx / 2048
    const int nb = (r >> 9) + 1;
    float4 s = *(const float4*)(g_scores + idx);
    for (int b = 1; b < nb; b++) {
        const float4 p = *(const float4*)(g_scores + (size_t)b * S_ * D_ + idx);
        s.x += p.x; s.y += p.y; s.z += p.z; s.w += p.w;
    }
    __half2 h0 = __floats2half2_rn(s.x, s.y);
    __half2 h1 = __floats2half2_rn(s.z, s.w);
    *(__half2*)(g_ctx + idx)     = h0;
    *(__half2*)(g_ctx + idx + 2) = h1;
}

// ===================== fp16 tensor-core GEMM (mma.sync) =====================
// C[M,N] = A[M,K] @ B[N,K]^T, fp16 in, fp32 accumulate.
// CTA: 128x128 tile, 256 thr (8 warps, 2x4 grid, 64x32/warp), BK=32,
// 3-stage cp.async pipeline, 2 CTAs/SM. 61.4 KB smem/CTA -> 123 KB/SM,
// leaving >100 KB so pointwise kernels can co-reside (overlap streams).
// EPI: 0=+bias, 1=+bias+gelu, 2=*scale, 3=none.  OUTF16: emit fp16.
// KSPLIT>0: bx = K-slice index (width KSPLIT); output fp32 partial buffer bx.
#define PITCHB 80                  // smem row pitch in bytes (32 fp16 + 16B pad)
#define ABYTES (128 * PITCHB)      // 10240 B per tile (A or B)
#define STAGEB (2 * ABYTES)        // 20480 B per stage
#define NSTAGE 3

template<int EPI, bool OUTF16, bool CSKIP, bool KLIM, int KSPLIT>
__global__ void __launch_bounds__(256, 2) gemm_mma(
    const __half* __restrict__ A, int lda, size_t astride,
    const __half* __restrict__ B, int ldb, size_t bstride,
    const float* __restrict__ bias,
    float* __restrict__ Cf, __half* __restrict__ Ch,
    int ldc, size_t cstride,
    int K, float scale)
{
    const int bx = blockIdx.x, by = blockIdx.y, bz = blockIdx.z;
    const int nblk = KSPLIT ? 0 : bx;          // N-tile index
    if (CSKIP && nblk > by) return;
    A += (size_t)bz * astride;
    B += (size_t)bz * bstride;
    if (OUTF16) Ch += (size_t)bz * cstride;
    else        Cf += (size_t)bz * cstride;

    int kend = K;
    if (KLIM) { int kl = (by + 1) * 128; if (kl < kend) kend = kl; }
    int kbeg = 0;
    if (KSPLIT) {
        kbeg = bx * KSPLIT;
        if (kbeg >= kend) return;
        if (kend > kbeg + KSPLIT) kend = kbeg + KSPLIT;
        Cf += (size_t)bx * ((size_t)S_ * D_);  // partial buffer bx
    }
    const int NC = (kend - kbeg) >> 5;   // chunks of 32

    extern __shared__ char smem[];
    const uint32_t sbase = smem_to_u32(smem);
    const int tid = threadIdx.x;
    const int lane = tid & 31, wid = tid >> 5;
    const int wm = wid & 1, wn = wid >> 1;   // 2 x 4 warp grid

    const __half* arow = A + (size_t)(by * 128) * lda + kbeg;
    const __half* brow = B + (size_t)(nblk * 128) * ldb + kbeg;

    auto load_chunk = [&](int c) {
        const uint32_t sb = sbase + (uint32_t)(c % NSTAGE) * STAGEB;
        const int k0 = c << 5;
        #pragma unroll
        for (int t = 0; t < 2; t++) {            // A+B: 512 16B segs each
            const int idx = tid + t * 256;       // 0..511
            const int r = idx >> 2, seg = idx & 3;
            const uint32_t d = sb + (uint32_t)(r * PITCHB + seg * 16);
            cpa16(d,          arow + (size_t)r * lda + k0 + seg * 8);
            cpa16(d + ABYTES, brow + (size_t)r * ldb + k0 + seg * 8);
        }
        asm volatile("cp.async.commit_group;" ::: "memory");
    };

    float acc[4][4][4];
    #pragma unroll
    for (int i = 0; i < 4; i++)
        #pragma unroll
        for (int j = 0; j < 4; j++)
            #pragma unroll
            for (int q = 0; q < 4; q++) acc[i][j][q] = 0.f;

    load_chunk(0);
    if (NC > 1) load_chunk(1);
    if (NC > 2) load_chunk(2);

    const int lsel = lane & 15;
    const uint32_t a_base = (uint32_t)((wm * 64 + (lane & 15)) * PITCHB + (lane >> 4) * 16);
    const uint32_t b_base = (uint32_t)(ABYTES + (wn * 32 + (lsel & 7)) * PITCHB + (lsel >> 3) * 16);

    for (int c = 0; c < NC; c++) {
        const int rem = NC - 1 - c;   // groups committed after c
        if (rem >= 2)      asm volatile("cp.async.wait_group 2;" ::: "memory");
        else if (rem == 1) asm volatile("cp.async.wait_group 1;" ::: "memory");
        else               asm volatile("cp.async.wait_group 0;" ::: "memory");
        __syncthreads();

        const uint32_t sb = sbase + (uint32_t)(c % NSTAGE) * STAGEB;
        #pragma unroll
        for (int k16 = 0; k16 < 2; k16++) {
            const uint32_t kb = (uint32_t)(k16 * 32);
            uint32_t bf[4][2];
            #pragma unroll
            for (int nt = 0; nt < 4; nt++)
                ldsm_x2(bf[nt][0], bf[nt][1],
                        sb + b_base + (uint32_t)(nt * 8 * PITCHB) + kb);
            #pragma unroll
            for (int mt = 0; mt < 4; mt++) {
                uint32_t af[4];
                ldsm_x4(af[0], af[1], af[2], af[3],
                        sb + a_base + (uint32_t)(mt * 16 * PITCHB) + kb);
                #pragma unroll
                for (int nt = 0; nt < 4; nt++)
                    mma_f16(acc[mt][nt], af, bf[nt]);
            }
        }
        __syncthreads();           // all warps done with stage (c % NSTAGE)
        if (c + 3 < NC) load_chunk(c + 3);
    }

    // -------- epilogue --------------------------------------------------------
    const int r_in = wm * 64 + (lane >> 2);
    const int c_in = wn * 32 + (lane & 3) * 2;
    #pragma unroll
    for (int mt = 0; mt < 4; mt++) {
        #pragma unroll
        for (int half = 0; half < 2; half++) {
            const int grow = by * 128 + r_in + mt * 16 + half * 8;
            #pragma unroll
            for (int nt = 0; nt < 4; nt++) {
                const int gcol = nblk * 128 + c_in + nt * 8;
                float v0 = acc[mt][nt][half * 2 + 0];
                float v1 = acc[mt][nt][half * 2 + 1];
                if (EPI == 0) {
                    v0 += bias[gcol]; v1 += bias[gcol + 1];
                } else if (EPI == 1) {
                    v0 += bias[gcol]; v1 += bias[gcol + 1];
                    const float cst = 0.7978845608028654f;
                    float t0 = tanhf(cst * (v0 + 0.044715f * v0 * v0 * v0));
                    float t1 = tanhf(cst * (v1 + 0.044715f * v1 * v1 * v1));
                    v0 = 0.5f * v0 * (1.0f + t0);
                    v1 = 0.5f * v1 * (1.0f + t1);
                } else if (EPI == 2) {
                    v0 *= scale; v1 *= scale;
                }
                if (OUTF16) {
                    *(__half2*)(Ch + (size_t)grow * ldc + gcol) =
                        __floats2half2_rn(v0, v1);
                } else {
                    float2 f; f.x = v0; f.y = v1;
                    *(float2*)(Cf + (size_t)grow * ldc + gcol) = f;
                }
            }
        }
    }
}

// ===================== driver ===============================================
extern "C" void kernel_launch(void* const* d_in, const int* in_sizes, int n_in,
                              void* d_out, int out_size)
{
    (void)in_sizes; (void)n_in; (void)out_size;
    const float* x        = (const float*)d_in[0];
    const float* Wqkv     = (const float*)d_in[2];
    const float* bqkv     = (const float*)d_in[3];
    const float* Wo       = (const float*)d_in[4];
    const float* bo       = (const float*)d_in[5];
    const float* W1       = (const float*)d_in[6];
    const float* b1       = (const float*)d_in[7];
    const float* W2       = (const float*)d_in[8];
    const float* b2       = (const float*)d_in[9];
    const float* g_ln_in  = (const float*)d_in[10];
    const float* b_ln_in  = (const float*)d_in[11];
    const float* g_s1     = (const float*)d_in[12];
    const float* b_s1     = (const float*)d_in[13];
    const float* g_ln_out = (const float*)d_in[14];
    const float* b_ln_out = (const float*)d_in[15];
    const float* g_s2     = (const float*)d_in[16];
    const float* b_s2     = (const float*)d_in[17];
    float* out = (float*)d_out;

    float *psc, *ptmp, *px1;
    __half *ph, *pq, *pp, *pv, *pc, *pm, *wq, *wo, *w1, *w2;
    cudaGetSymbolAddress((void**)&psc, g_scores);
    cudaGetSymbolAddress((void**)&ptmp, g_tmp);
    cudaGetSymbolAddress((void**)&px1, g_x1);
    cudaGetSymbolAddress((void**)&ph, g_h);
    cudaGetSymbolAddress((void**)&pq, g_qkv);
    cudaGetSymbolAddress((void**)&pp, g_p);
    cudaGetSymbolAddress((void**)&pv, g_vt);
    cudaGetSymbolAddress((void**)&pc, g_ctx);
    cudaGetSymbolAddress((void**)&pm, g_m1);
    cudaGetSymbolAddress((void**)&wq, g_wq);
    cudaGetSymbolAddress((void**)&wo, g_wo);
    cudaGetSymbolAddress((void**)&w1, g_w1);
    cudaGetSymbolAddress((void**)&w2, g_w2);

    const int SMEM = NSTAGE * STAGEB;  // 61440
    cudaFuncSetAttribute(gemm_mma<0, true , false, false, 0>,
                         cudaFuncAttributeMaxDynamicSharedMemorySize, SMEM);
    cudaFuncSetAttribute(gemm_mma<2, true , true , false, 0>,
                         cudaFuncAttributeMaxDynamicSharedMemorySize, SMEM);
    cudaFuncSetAttribute(gemm_mma<3, false, false, true , 512>,
                         cudaFuncAttributeMaxDynamicSharedMemorySize, SMEM);
    cudaFuncSetAttribute(gemm_mma<0, false, false, false, 0>,
                         cudaFuncAttributeMaxDynamicSharedMemorySize, SMEM);
    cudaFuncSetAttribute(gemm_mma<1, true , false, false, 0>,
                         cudaFuncAttributeMaxDynamicSharedMemorySize, SMEM);

    // Side stream + events for overlap (capture-time only).
    cudaStream_t s2;
    cudaStreamCreateWithFlags(&s2, cudaStreamNonBlocking);
    cudaEvent_t eFork, eQKV, eScL, eScH, eSmL, eSmH;
    cudaEventCreateWithFlags(&eFork, cudaEventDisableTiming);
    cudaEventCreateWithFlags(&eQKV , cudaEventDisableTiming);
    cudaEventCreateWithFlags(&eScL , cudaEventDisableTiming);
    cudaEventCreateWithFlags(&eScH , cudaEventDisableTiming);
    cudaEventCreateWithFlags(&eSmL , cudaEventDisableTiming);
    cudaEventCreateWithFlags(&eSmH , cudaEventDisableTiming);

    const dim3 cvblk(32, 8);
    const float iscale = 0.08838834764831845f;

    // ---- main: prerequisites of QKV ----------------------------------------
    convw_kernel<<<dim3(QKV3 / 32, D_ / 64), cvblk>>>(Wqkv, D_, QKV3, wq);   // 1
    ln_kernel<true><<<S_, 256>>>(x, g_ln_in, b_ln_in, nullptr, nullptr, ph); // 2
    cudaEventRecord(eFork, 0);
    cudaStreamWaitEvent(s2, eFork, 0);
    // ---- s2: weight converts overlap QKV ------------------------------------
    convw_kernel<<<dim3(D_ / 32, D_ / 64), cvblk, 0, s2>>>(Wo, D_, D_, wo);  // 3
    // ---- main: QKV GEMM  <-- profiled launch #4 -----------------------------
    gemm_mma<0, true, false, false, 0><<<dim3(QKV3 / 128, S_ / 128, 1), 256, SMEM>>>(
        ph, D_, 0, wq, D_, 0, bqkv, nullptr, pq, QKV3, 0, D_, 0.f);          // 4
    cudaEventRecord(eQKV, 0);
    convw_kernel<<<dim3(DFF / 32, D_ / 64), cvblk, 0, s2>>>(W1, D_, DFF, w1);// 5
    convw_kernel<<<dim3(D_ / 32, DFF / 64), cvblk, 0, s2>>>(W2, DFF, D_, w2);// 6
    cudaStreamWaitEvent(s2, eQKV, 0);
    vtrans_kernel<<<dim3(S_ / 32, DH / 32, NH), cvblk, 0, s2>>>();           // 7
    // ---- main: scores in two head-halves ------------------------------------
    gemm_mma<2, true, true, false, 0><<<dim3(S_ / 128, S_ / 128, 8), 256, SMEM>>>(
        pq, QKV3, (size_t)DH, pq + D_, QKV3, (size_t)DH,
        nullptr, nullptr, pp, S_, (size_t)S_ * S_, DH, iscale);              // 8
    cudaEventRecord(eScL, 0);
    gemm_mma<2, true, true, false, 0><<<dim3(S_ / 128, S_ / 128, 8), 256, SMEM>>>(
        pq + 8 * DH, QKV3, (size_t)DH, pq + D_ + 8 * DH, QKV3, (size_t)DH,
        nullptr, nullptr, pp + (size_t)8 * S_ * S_, S_, (size_t)S_ * S_,
        DH, iscale);                                                         // 9
    cudaEventRecord(eScH, 0);
    // ---- s2: softmax halves overlap scores_hi / P@V_lo ----------------------
    cudaStreamWaitEvent(s2, eScL, 0);
    softmax_kernel<<<dim3(S_, 8), 256, 0, s2>>>(0);                          // 10
    cudaEventRecord(eSmL, s2);
    cudaStreamWaitEvent(s2, eScH, 0);
    softmax_kernel<<<dim3(S_, 8), 256, 0, s2>>>(8);                          // 11
    cudaEventRecord(eSmH, s2);
    // ---- main: P@V halves ---------------------------------------------------
    cudaStreamWaitEvent(0, eSmL, 0);
    gemm_mma<3, false, false, true, 512><<<dim3(4, S_ / 128, 8), 256, SMEM>>>(
        pp, S_, (size_t)S_ * S_, pv, S_, (size_t)DH * S_,
        nullptr, psc, nullptr, D_, (size_t)DH, S_, 0.f);                     // 12
    cudaStreamWaitEvent(0, eSmH, 0);
    gemm_mma<3, false, false, true, 512><<<dim3(4, S_ / 128, 8), 256, SMEM>>>(
        pp + (size_t)8 * S_ * S_, S_, (size_t)S_ * S_,
        pv + (size_t)8 * DH * S_, S_, (size_t)DH * S_,
        nullptr, psc + 8 * DH, nullptr, D_, (size_t)DH, S_, 0.f);            // 13
    combine_pv_kernel<<<(S_ * D_) / (256 * 4), 256>>>();                     // 14
    // ---- main: tail (s2 fully joined via eSmH transitively) -----------------
    gemm_mma<0, false, false, false, 0><<<dim3(D_ / 128, S_ / 128, 1), 256, SMEM>>>(
        pc, D_, 0, wo, D_, 0, bo, ptmp, nullptr, D_, 0, D_, 0.f);            // 15
    ln_res_ln_kernel<<<S_, 256>>>(ptmp, g_s1, b_s1, x, g_ln_out, b_ln_out,
                                  px1, ph);                                  // 16
    gemm_mma<1, true, false, false, 0><<<dim3(DFF / 128, S_ / 128, 1), 256, SMEM>>>(
        ph, D_, 0, w1, D_, 0, b1, nullptr, pm, DFF, 0, D_, 0.f);             // 17
    gemm_mma<0, false, false, false, 0><<<dim3(D_ / 128, S_ / 128, 1), 256, SMEM>>>(
        pm, DFF, 0, w2, DFF, 0, b2, ptmp, nullptr, D_, 0, DFF, 0.f);         // 18
    ln_kernel<false><<<S_, 256>>>(ptmp, g_s2, b_s2, px1, out, nullptr);      // 19
}

// round 14
// speedup vs baseline: 1.0192x; 1.0192x over previous
#include <cuda_runtime.h>
#include <cuda_fp16.h>
#include <math.h>
#include <stdint.h>
#include <stddef.h>

// Problem dims (fixed)
#define S_   2048
#define D_   2048
#define NH   16
#define DH   128
#define QKV3 6144
#define DFF  8192

// ===================== low-level helpers (sm_100 baseline ISA) ==============
__device__ __forceinline__ uint32_t smem_to_u32(const void* p) {
    uint32_t a;
    asm("{ .reg .u64 t; cvta.to.shared.u64 t, %1; cvt.u32.u64 %0, t; }"
        : "=r"(a) : "l"(p));
    return a;
}
__device__ __forceinline__ void cpa16(uint32_t dst, const void* src) {
    asm volatile("cp.async.cg.shared.global [%0], [%1], 16;" :: "r"(dst), "l"(src));
}
__device__ __forceinline__ void ldsm_x4(uint32_t& r0, uint32_t& r1,
                                        uint32_t& r2, uint32_t& r3, uint32_t addr) {
    asm volatile("ldmatrix.sync.aligned.m8n8.x4.shared.b16 {%0,%1,%2,%3}, [%4];"
                 : "=r"(r0), "=r"(r1), "=r"(r2), "=r"(r3) : "r"(addr));
}
__device__ __forceinline__ void ldsm_x2(uint32_t& r0, uint32_t& r1, uint32_t addr) {
    asm volatile("ldmatrix.sync.aligned.m8n8.x2.shared.b16 {%0,%1}, [%2];"
                 : "=r"(r0), "=r"(r1) : "r"(addr));
}
__device__ __forceinline__ void mma_f16(float* c, const uint32_t* a, const uint32_t* b) {
    asm volatile("mma.sync.aligned.m16n8k16.row.col.f32.f16.f16.f32 "
                 "{%0,%1,%2,%3},{%4,%5,%6,%7},{%8,%9},{%0,%1,%2,%3};"
                 : "+f"(c[0]), "+f"(c[1]), "+f"(c[2]), "+f"(c[3])
                 : "r"(a[0]), "r"(a[1]), "r"(a[2]), "r"(a[3]), "r"(b[0]), "r"(b[1]));
}

// ===================== scratch (device globals) =============================
__device__ __align__(128) float g_scores[(size_t)4 * S_ * D_ + 128];
__device__ __align__(128) float g_tmp[(size_t)S_ * D_];
__device__ __align__(128) float g_x1[(size_t)S_ * D_];

__device__ __align__(128) __half g_h[(size_t)S_ * D_];
__device__ __align__(128) __half g_qkv[(size_t)S_ * QKV3];
__device__ __align__(128) __half g_p[(size_t)NH * S_ * S_];      // scores then p
__device__ __align__(128) __half g_vt[(size_t)NH * DH * S_];
__device__ __align__(128) __half g_ctx[(size_t)S_ * D_];
__device__ __align__(128) __half g_m1[(size_t)S_ * DFF];

__device__ __align__(128) __half g_wq[(size_t)QKV3 * D_];
__device__ __align__(128) __half g_wo[(size_t)D_ * D_];
__device__ __align__(128) __half g_w1[(size_t)DFF * D_];
__device__ __align__(128) __half g_w2[(size_t)D_ * DFF];

// ===================== reductions ===========================================
__device__ __forceinline__ float blockReduceSum(float v) {
    __shared__ float red[32];
    __syncthreads();
    int lane = threadIdx.x & 31, w = threadIdx.x >> 5;
    #pragma unroll
    for (int o = 16; o; o >>= 1) v += __shfl_xor_sync(0xffffffffu, v, o);
    if (lane == 0) red[w] = v;
    __syncthreads();
    if (w == 0) {
        float r = (lane < ((blockDim.x + 31) >> 5)) ? red[lane] : 0.f;
        #pragma unroll
        for (int o = 16; o; o >>= 1) r += __shfl_xor_sync(0xffffffffu, r, o);
        if (lane == 0) red[0] = r;
    }
    __syncthreads();
    return red[0];
}
__device__ __forceinline__ float blockReduceMax(float v) {
    __shared__ float red[32];
    __syncthreads();
    int lane = threadIdx.x & 31, w = threadIdx.x >> 5;
    #pragma unroll
    for (int o = 16; o; o >>= 1) v = fmaxf(v, __shfl_xor_sync(0xffffffffu, v, o));
    if (lane == 0) red[w] = v;
    __syncthreads();
    if (w == 0) {
        float r = (lane < ((blockDim.x + 31) >> 5)) ? red[lane] : -3.0e38f;
        #pragma unroll
        for (int o = 16; o; o >>= 1) r = fmaxf(r, __shfl_xor_sync(0xffffffffu, r, o));
        if (lane == 0) red[0] = r;
    }
    __syncthreads();
    return red[0];
}

// ===================== LayerNorm ============================================
template<bool TOF16>
__global__ void __launch_bounds__(256) ln_kernel(
    const float* __restrict__ in, const float* __restrict__ gam,
    const float* __restrict__ bet, const float* __restrict__ res,
    float* __restrict__ outf, __half* __restrict__ oh)
{
    const int row = blockIdx.x;
    const float* x = in + (size_t)row * D_;
    __shared__ float sm[D_];
    float s = 0.f;
    for (int j = threadIdx.x; j < D_; j += blockDim.x) {
        float v = x[j]; sm[j] = v; s += v;
    }
    const float mu = blockReduceSum(s) * (1.0f / D_);
    float sq = 0.f;
    for (int j = threadIdx.x; j < D_; j += blockDim.x) {
        float d = sm[j] - mu; sq += d * d;
    }
    const float var = blockReduceSum(sq) * (1.0f / D_);
    const float inv = rsqrtf(var + 1e-5f);
    for (int j = threadIdx.x; j < D_; j += blockDim.x) {
        float v = (sm[j] - mu) * inv * gam[j] + bet[j];
        if (TOF16) {
            oh[(size_t)row * D_ + j] = __float2half_rn(v);
        } else {
            if (res) v += res[(size_t)row * D_ + j];
            outf[(size_t)row * D_ + j] = v;
        }
    }
}

// ===================== fused: x1 = x + LN(a), ho = LN(x1) -> fp16 ==========
__global__ void __launch_bounds__(256) ln_res_ln_kernel(
    const float* __restrict__ a, const float* __restrict__ g1,
    const float* __restrict__ b1, const float* __restrict__ x,
    const float* __restrict__ g2, const float* __restrict__ b2,
    float* __restrict__ x1_out, __half* __restrict__ ho)
{
    const int row = blockIdx.x;
    const float* ar = a + (size_t)row * D_;
    __shared__ float sm[D_];
    float s = 0.f;
    for (int j = threadIdx.x; j < D_; j += blockDim.x) {
        float v = ar[j]; sm[j] = v; s += v;
    }
    float mu = blockReduceSum(s) * (1.0f / D_);
    float sq = 0.f;
    for (int j = threadIdx.x; j < D_; j += blockDim.x) {
        float d = sm[j] - mu; sq += d * d;
    }
    float var = blockReduceSum(sq) * (1.0f / D_);
    float inv = rsqrtf(var + 1e-5f);
    float s2 = 0.f;
    for (int j = threadIdx.x; j < D_; j += blockDim.x) {
        float v = (sm[j] - mu) * inv * g1[j] + b1[j] + x[(size_t)row * D_ + j];
        sm[j] = v;
        x1_out[(size_t)row * D_ + j] = v;
        s2 += v;
    }
    mu = blockReduceSum(s2) * (1.0f / D_);
    sq = 0.f;
    for (int j = threadIdx.x; j < D_; j += blockDim.x) {
        float d = sm[j] - mu; sq += d * d;
    }
    var = blockReduceSum(sq) * (1.0f / D_);
    inv = rsqrtf(var + 1e-5f);
    for (int j = threadIdx.x; j < D_; j += blockDim.x)
        ho[(size_t)row * D_ + j] =
            __float2half_rn((sm[j] - mu) * inv * g2[j] + b2[j]);
}

// ===================== causal softmax (in place, fp16) ======================
__global__ void __launch_bounds__(256) softmax_kernel(int h0)
{
    const int i = blockIdx.x;
    const int h = blockIdx.y + h0;
    const size_t base = ((size_t)h * S_ + i) * S_;
    __half* ph = g_p + base;
    const int n = i + 1;
    const int fill_end = ((i >> 7) + 1) << 7;   // next multiple of 128
    __shared__ float sm[S_];
    float m = -3.0e38f;
    for (int j = threadIdx.x; j < n; j += blockDim.x) {
        float v = __half2float(ph[j]); sm[j] = v; m = fmaxf(m, v);
    }
    m = blockReduceMax(m);
    float s = 0.f;
    for (int j = threadIdx.x; j < n; j += blockDim.x) {
        float e = expf(sm[j] - m); sm[j] = e; s += e;
    }
    const float inv = 1.0f / blockReduceSum(s);
    const __half z = __float2half_rn(0.f);
    for (int j = threadIdx.x; j < n; j += blockDim.x)
        ph[j] = __float2half_rn(sm[j] * inv);
    for (int j = n + threadIdx.x; j < fill_end; j += blockDim.x) ph[j] = z;
}

// ===================== weight convert + transpose ===========================
__global__ void __launch_bounds__(256) convw_kernel(
    const float* __restrict__ W, int K, int N, __half* __restrict__ o)
{
    __shared__ float t[64][33];
    const int n0 = blockIdx.x * 32, k0 = blockIdx.y * 64;
    const int tx = threadIdx.x, ty = threadIdx.y;  // 32 x 8
    #pragma unroll
    for (int j = 0; j < 8; j++)
        t[ty + j * 8][tx] = W[(size_t)(k0 + ty + j * 8) * N + n0 + tx];
    __syncthreads();
    #pragma unroll
    for (int j = 0; j < 4; j++) {
        const int n = ty + j * 8;
        __half2 hv = __floats2half2_rn(t[tx * 2][n], t[tx * 2 + 1][n]);
        *(__half2*)(o + (size_t)(n0 + n) * K + k0 + tx * 2) = hv;
    }
}

// ===================== V transpose (fp16) ===================================
__global__ void __launch_bounds__(256) vtrans_kernel()
{
    __shared__ __half th[32][33];
    const int h = blockIdx.z;
    const int s0 = blockIdx.x * 32, d0 = blockIdx.y * 32;
    const int tx = threadIdx.x, ty = threadIdx.y;
    #pragma unroll
    for (int j = 0; j < 4; j++)
        th[ty + j * 8][tx] =
            g_qkv[(size_t)(s0 + ty + j * 8) * QKV3 + 2 * D_ + h * DH + d0 + tx];
    __syncthreads();
    #pragma unroll
    for (int j = 0; j < 4; j++)
        g_vt[((size_t)h * DH + d0 + ty + j * 8) * S_ + s0 + tx] = th[tx][ty + j * 8];
}

// ===================== P@V partial combine (column half) ====================
// Processes columns [c0, c0+1024) of all rows. nb(row) = (row>>9)+1 buffers.
__global__ void __launch_bounds__(256) combine_pv_kernel(int c0)
{
    const size_t lin = ((size_t)blockIdx.x * 256 + threadIdx.x) * 4;
    const int r = (int)(lin >> 10);          // row = lin / 1024
    const int c = (int)(lin & 1023);
    const size_t idx = (size_t)r * D_ + c0 + c;
    const int nb = (r >> 9) + 1;
    float4 s = *(const float4*)(g_scores + idx);
    for (int b = 1; b < nb; b++) {
        const float4 p = *(const float4*)(g_scores + (size_t)b * S_ * D_ + idx);
        s.x += p.x; s.y += p.y; s.z += p.z; s.w += p.w;
    }
    __half2 h0 = __floats2half2_rn(s.x, s.y);
    __half2 h1 = __floats2half2_rn(s.z, s.w);
    *(__half2*)(g_ctx + idx)     = h0;
    *(__half2*)(g_ctx + idx + 2) = h1;
}

// ===================== fp16 tensor-core GEMM (mma.sync) =====================
// C[M,N] = A[M,K] @ B[N,K]^T, fp16 in, fp32 accumulate.
// CTA: 128x128 tile, 256 thr (8 warps, 2x4 grid, 64x32/warp), BK=64
// (4 k16 steps per stage), 3-stage cp.async pipeline, 2 CTAs/SM.
// EPI: 0=+bias, 1=+bias+gelu, 2=*scale, 3=none.  OUTF16: emit fp16.
// KSPLIT>0: bx = K-slice index (width KSPLIT); output fp32 partial buffer bx.
#define PITCHB 144                 // smem row pitch in bytes (64 fp16 + 16B pad)
#define ABYTES (128 * PITCHB)      // 18432 B per tile (A or B)
#define STAGEB (2 * ABYTES)        // 36864 B per stage
#define NSTAGE 3

template<int EPI, bool OUTF16, bool CSKIP, bool KLIM, int KSPLIT>
__global__ void __launch_bounds__(256, 2) gemm_mma(
    const __half* __restrict__ A, int lda, size_t astride,
    const __half* __restrict__ B, int ldb, size_t bstride,
    const float* __restrict__ bias,
    float* __restrict__ Cf, __half* __restrict__ Ch,
    int ldc, size_t cstride,
    int K, float scale)
{
    const int bx = blockIdx.x, by = blockIdx.y, bz = blockIdx.z;
    const int nblk = KSPLIT ? 0 : bx;          // N-tile index
    if (CSKIP && nblk > by) return;
    A += (size_t)bz * astride;
    B += (size_t)bz * bstride;
    if (OUTF16) Ch += (size_t)bz * cstride;
    else        Cf += (size_t)bz * cstride;

    int kend = K;
    if (KLIM) { int kl = (by + 1) * 128; if (kl < kend) kend = kl; }
    int kbeg = 0;
    if (KSPLIT) {
        kbeg = bx * KSPLIT;
        if (kbeg >= kend) return;
        if (kend > kbeg + KSPLIT) kend = kbeg + KSPLIT;
        Cf += (size_t)bx * ((size_t)S_ * D_);  // partial buffer bx
    }
    const int NC = (kend - kbeg) >> 6;   // chunks of 64

    extern __shared__ char smem[];
    const uint32_t sbase = smem_to_u32(smem);
    const int tid = threadIdx.x;
    const int lane = tid & 31, wid = tid >> 5;
    const int wm = wid & 1, wn = wid >> 1;   // 2 x 4 warp grid

    const __half* arow = A + (size_t)(by * 128) * lda + kbeg;
    const __half* brow = B + (size_t)(nblk * 128) * ldb + kbeg;

    auto load_chunk = [&](int c) {
        const uint32_t sb = sbase + (uint32_t)(c % NSTAGE) * STAGEB;
        const int k0 = c << 6;
        #pragma unroll
        for (int t = 0; t < 4; t++) {            // A+B: 1024 16B segs each
            const int idx = tid + t * 256;       // 0..1023
            const int r = idx >> 3, seg = idx & 7;
            const uint32_t d = sb + (uint32_t)(r * PITCHB + seg * 16);
            cpa16(d,          arow + (size_t)r * lda + k0 + seg * 8);
            cpa16(d + ABYTES, brow + (size_t)r * ldb + k0 + seg * 8);
        }
        asm volatile("cp.async.commit_group;" ::: "memory");
    };

    float acc[4][4][4];
    #pragma unroll
    for (int i = 0; i < 4; i++)
        #pragma unroll
        for (int j = 0; j < 4; j++)
            #pragma unroll
            for (int q = 0; q < 4; q++) acc[i][j][q] = 0.f;

    load_chunk(0);
    if (NC > 1) load_chunk(1);
    if (NC > 2) load_chunk(2);

    const int lsel = lane & 15;
    const uint32_t a_base = (uint32_t)((wm * 64 + (lane & 15)) * PITCHB + (lane >> 4) * 16);
    const uint32_t b_base = (uint32_t)(ABYTES + (wn * 32 + (lsel & 7)) * PITCHB + (lsel >> 3) * 16);

    for (int c = 0; c < NC; c++) {
        const int rem = NC - 1 - c;   // groups committed after c
        if (rem >= 2)      asm volatile("cp.async.wait_group 2;" ::: "memory");
        else if (rem == 1) asm volatile("cp.async.wait_group 1;" ::: "memory");
        else               asm volatile("cp.async.wait_group 0;" ::: "memory");
        __syncthreads();

        const uint32_t sb = sbase + (uint32_t)(c % NSTAGE) * STAGEB;
        #pragma unroll
        for (int k16 = 0; k16 < 4; k16++) {
            const uint32_t kb = (uint32_t)(k16 * 32);
            uint32_t bf[4][2];
            #pragma unroll
            for (int nt = 0; nt < 4; nt++)
                ldsm_x2(bf[nt][0], bf[nt][1],
                        sb + b_base + (uint32_t)(nt * 8 * PITCHB) + kb);
            #pragma unroll
            for (int mt = 0; mt < 4; mt++) {
                uint32_t af[4];
                ldsm_x4(af[0], af[1], af[2], af[3],
                        sb + a_base + (uint32_t)(mt * 16 * PITCHB) + kb);
                #pragma unroll
                for (int nt = 0; nt < 4; nt++)
                    mma_f16(acc[mt][nt], af, bf[nt]);
            }
        }
        __syncthreads();           // all warps done with stage (c % NSTAGE)
        if (c + 3 < NC) load_chunk(c + 3);
    }

    // -------- epilogue --------------------------------------------------------
    const int r_in = wm * 64 + (lane >> 2);
    const int c_in = wn * 32 + (lane & 3) * 2;
    #pragma unroll
    for (int mt = 0; mt < 4; mt++) {
        #pragma unroll
        for (int half = 0; half < 2; half++) {
            const int grow = by * 128 + r_in + mt * 16 + half * 8;
            #pragma unroll
            for (int nt = 0; nt < 4; nt++) {
                const int gcol = nblk * 128 + c_in + nt * 8;
                float v0 = acc[mt][nt][half * 2 + 0];
                float v1 = acc[mt][nt][half * 2 + 1];
                if (EPI == 0) {
                    v0 += bias[gcol]; v1 += bias[gcol + 1];
                } else if (EPI == 1) {
                    v0 += bias[gcol]; v1 += bias[gcol + 1];
                    const float cst = 0.7978845608028654f;
                    float t0 = tanhf(cst * (v0 + 0.044715f * v0 * v0 * v0));
                    float t1 = tanhf(cst * (v1 + 0.044715f * v1 * v1 * v1));
                    v0 = 0.5f * v0 * (1.0f + t0);
                    v1 = 0.5f * v1 * (1.0f + t1);
                } else if (EPI == 2) {
                    v0 *= scale; v1 *= scale;
                }
                if (OUTF16) {
                    *(__half2*)(Ch + (size_t)grow * ldc + gcol) =
                        __floats2half2_rn(v0, v1);
                } else {
                    float2 f; f.x = v0; f.y = v1;
                    *(float2*)(Cf + (size_t)grow * ldc + gcol) = f;
                }
            }
        }
    }
}

// ===================== driver ===============================================
extern "C" void kernel_launch(void* const* d_in, const int* in_sizes, int n_in,
                              void* d_out, int out_size)
{
    (void)in_sizes; (void)n_in; (void)out_size;
    const float* x        = (const float*)d_in[0];
    const float* Wqkv     = (const float*)d_in[2];
    const float* bqkv     = (const float*)d_in[3];
    const float* Wo       = (const float*)d_in[4];
    const float* bo       = (const float*)d_in[5];
    const float* W1       = (const float*)d_in[6];
    const float* b1       = (const float*)d_in[7];
    const float* W2       = (const float*)d_in[8];
    const float* b2       = (const float*)d_in[9];
    const float* g_ln_in  = (const float*)d_in[10];
    const float* b_ln_in  = (const float*)d_in[11];
    const float* g_s1     = (const float*)d_in[12];
    const float* b_s1     = (const float*)d_in[13];
    const float* g_ln_out = (const float*)d_in[14];
    const float* b_ln_out = (const float*)d_in[15];
    const float* g_s2     = (const float*)d_in[16];
    const float* b_s2     = (const float*)d_in[17];
    float* out = (float*)d_out;

    float *psc, *ptmp, *px1;
    __half *ph, *pq, *pp, *pv, *pc, *pm, *wq, *wo, *w1, *w2;
    cudaGetSymbolAddress((void**)&psc, g_scores);
    cudaGetSymbolAddress((void**)&ptmp, g_tmp);
    cudaGetSymbolAddress((void**)&px1, g_x1);
    cudaGetSymbolAddress((void**)&ph, g_h);
    cudaGetSymbolAddress((void**)&pq, g_qkv);
    cudaGetSymbolAddress((void**)&pp, g_p);
    cudaGetSymbolAddress((void**)&pv, g_vt);
    cudaGetSymbolAddress((void**)&pc, g_ctx);
    cudaGetSymbolAddress((void**)&pm, g_m1);
    cudaGetSymbolAddress((void**)&wq, g_wq);
    cudaGetSymbolAddress((void**)&wo, g_wo);
    cudaGetSymbolAddress((void**)&w1, g_w1);
    cudaGetSymbolAddress((void**)&w2, g_w2);

    const int SMEM = NSTAGE * STAGEB;  // 110592
    cudaFuncSetAttribute(gemm_mma<0, true , false, false, 0>,
                         cudaFuncAttributeMaxDynamicSharedMemorySize, SMEM);
    cudaFuncSetAttribute(gemm_mma<2, true , true , false, 0>,
                         cudaFuncAttributeMaxDynamicSharedMemorySize, SMEM);
    cudaFuncSetAttribute(gemm_mma<3, false, false, true , 512>,
                         cudaFuncAttributeMaxDynamicSharedMemorySize, SMEM);
    cudaFuncSetAttribute(gemm_mma<0, false, false, false, 0>,
                         cudaFuncAttributeMaxDynamicSharedMemorySize, SMEM);
    cudaFuncSetAttribute(gemm_mma<1, true , false, false, 0>,
                         cudaFuncAttributeMaxDynamicSharedMemorySize, SMEM);

    // Side stream + events (capture-time only; no device memory involved).
    cudaStream_t s2;
    cudaStreamCreateWithFlags(&s2, cudaStreamNonBlocking);
    cudaEvent_t eFork, eLN, eQKV, eSc[4], eSm[4], ePv1, eCmbL;
    cudaEventCreateWithFlags(&eFork, cudaEventDisableTiming);
    cudaEventCreateWithFlags(&eLN  , cudaEventDisableTiming);
    cudaEventCreateWithFlags(&eQKV , cudaEventDisableTiming);
    for (int i = 0; i < 4; i++) {
        cudaEventCreateWithFlags(&eSc[i], cudaEventDisableTiming);
        cudaEventCreateWithFlags(&eSm[i], cudaEventDisableTiming);
    }
    cudaEventCreateWithFlags(&ePv1 , cudaEventDisableTiming);
    cudaEventCreateWithFlags(&eCmbL, cudaEventDisableTiming);

    const dim3 cvblk(32, 8);
    const float iscale = 0.08838834764831845f;

    // ---- prologue: convw(Wqkv) on main, ln on s2 (parallel) -----------------
    cudaEventRecord(eFork, 0);
    cudaStreamWaitEvent(s2, eFork, 0);
    convw_kernel<<<dim3(QKV3 / 32, D_ / 64), cvblk>>>(Wqkv, D_, QKV3, wq);   // 1
    ln_kernel<true><<<S_, 256, 0, s2>>>(x, g_ln_in, b_ln_in,
                                        nullptr, nullptr, ph);               // 2
    cudaEventRecord(eLN, s2);
    convw_kernel<<<dim3(D_ / 32, D_ / 64), cvblk, 0, s2>>>(Wo, D_, D_, wo);  // 3
    cudaStreamWaitEvent(0, eLN, 0);
    // ---- main: QKV GEMM  <-- profiled launch #4 -----------------------------
    gemm_mma<0, true, false, false, 0><<<dim3(QKV3 / 128, S_ / 128, 1), 256, SMEM>>>(
        ph, D_, 0, wq, D_, 0, bqkv, nullptr, pq, QKV3, 0, D_, 0.f);          // 4
    cudaEventRecord(eQKV, 0);
    convw_kernel<<<dim3(DFF / 32, D_ / 64), cvblk, 0, s2>>>(W1, D_, DFF, w1);// 5
    convw_kernel<<<dim3(D_ / 32, DFF / 64), cvblk, 0, s2>>>(W2, DFF, D_, w2);// 6
    cudaStreamWaitEvent(s2, eQKV, 0);
    vtrans_kernel<<<dim3(S_ / 32, DH / 32, NH), cvblk, 0, s2>>>();           // 7
    // ---- attention: 4-stage head-quarter pipeline ---------------------------
    for (int q = 0; q < 4; q++) {                                            // 8-11
        const int h0 = q * 4;
        gemm_mma<2, true, true, false, 0><<<dim3(S_ / 128, S_ / 128, 4), 256, SMEM>>>(
            pq + h0 * DH, QKV3, (size_t)DH,
            pq + D_ + h0 * DH, QKV3, (size_t)DH,
            nullptr, nullptr, pp + (size_t)h0 * S_ * S_, S_, (size_t)S_ * S_,
            DH, iscale);
        cudaEventRecord(eSc[q], 0);
    }
    for (int q = 0; q < 4; q++) {                                            // 12-15
        cudaStreamWaitEvent(s2, eSc[q], 0);
        softmax_kernel<<<dim3(S_, 4), 256, 0, s2>>>(q * 4);
        cudaEventRecord(eSm[q], s2);
    }
    for (int q = 0; q < 4; q++) {                                            // 16-19
        const int h0 = q * 4;
        cudaStreamWaitEvent(0, eSm[q], 0);
        gemm_mma<3, false, false, true, 512><<<dim3(4, S_ / 128, 4), 256, SMEM>>>(
            pp + (size_t)h0 * S_ * S_, S_, (size_t)S_ * S_,
            pv + (size_t)h0 * DH * S_, S_, (size_t)DH * S_,
            nullptr, psc + h0 * DH, nullptr, D_, (size_t)DH, S_, 0.f);
        if (q == 1) cudaEventRecord(ePv1, 0);
    }
    // combine: low columns on s2 (overlaps pv q2/q3), high columns on main
    cudaStreamWaitEvent(s2, ePv1, 0);
    combine_pv_kernel<<<(S_ * 1024) / (256 * 4), 256, 0, s2>>>(0);           // 20
    cudaEventRecord(eCmbL, s2);
    combine_pv_kernel<<<(S_ * 1024) / (256 * 4), 256>>>(1024);               // 21
    cudaStreamWaitEvent(0, eCmbL, 0);
    // ---- tail ---------------------------------------------------------------
    gemm_mma<0, false, false, false, 0><<<dim3(D_ / 128, S_ / 128, 1), 256, SMEM>>>(
        pc, D_, 0, wo, D_, 0, bo, ptmp, nullptr, D_, 0, D_, 0.f);            // 22
    ln_res_ln_kernel<<<S_, 256>>>(ptmp, g_s1, b_s1, x, g_ln_out, b_ln_out,
                                  px1, ph);                                  // 23
    gemm_mma<1, true, false, false, 0><<<dim3(DFF / 128, S_ / 128, 1), 256, SMEM>>>(
        ph, D_, 0, w1, D_, 0, b1, nullptr, pm, DFF, 0, D_, 0.f);             // 24
    gemm_mma<0, false, false, false, 0><<<dim3(D_ / 128, S_ / 128, 1), 256, SMEM>>>(
        pm, DFF, 0, w2, DFF, 0, b2, ptmp, nullptr, D_, 0, DFF, 0.f);         // 25
    ln_kernel<false><<<S_, 256>>>(ptmp, g_s2, b_s2, px1, out, nullptr);      // 26
}

// round 15
// speedup vs baseline: 1.0305x; 1.0112x over previous
#include <cuda_runtime.h>
#include <cuda_fp16.h>
#include <math.h>
#include <stdint.h>
#include <stddef.h>

// Problem dims (fixed)
#define S_   2048
#define D_   2048
#define NH   16
#define DH   128
#define QKV3 6144
#define DFF  8192

// ===================== low-level helpers (sm_100 baseline ISA) ==============
__device__ __forceinline__ uint32_t smem_to_u32(const void* p) {
    uint32_t a;
    asm("{ .reg .u64 t; cvta.to.shared.u64 t, %1; cvt.u32.u64 %0, t; }"
        : "=r"(a) : "l"(p));
    return a;
}
__device__ __forceinline__ void cpa16(uint32_t dst, const void* src) {
    asm volatile("cp.async.cg.shared.global [%0], [%1], 16;" :: "r"(dst), "l"(src));
}
__device__ __forceinline__ void ldsm_x4(uint32_t& r0, uint32_t& r1,
                                        uint32_t& r2, uint32_t& r3, uint32_t addr) {
    asm volatile("ldmatrix.sync.aligned.m8n8.x4.shared.b16 {%0,%1,%2,%3}, [%4];"
                 : "=r"(r0), "=r"(r1), "=r"(r2), "=r"(r3) : "r"(addr));
}
__device__ __forceinline__ void ldsm_x2(uint32_t& r0, uint32_t& r1, uint32_t addr) {
    asm volatile("ldmatrix.sync.aligned.m8n8.x2.shared.b16 {%0,%1}, [%2];"
                 : "=r"(r0), "=r"(r1) : "r"(addr));
}
__device__ __forceinline__ void mma_f16(float* c, const uint32_t* a, const uint32_t* b) {
    asm volatile("mma.sync.aligned.m16n8k16.row.col.f32.f16.f16.f32 "
                 "{%0,%1,%2,%3},{%4,%5,%6,%7},{%8,%9},{%0,%1,%2,%3};"
                 : "+f"(c[0]), "+f"(c[1]), "+f"(c[2]), "+f"(c[3])
                 : "r"(a[0]), "r"(a[1]), "r"(a[2]), "r"(a[3]), "r"(b[0]), "r"(b[1]));
}

// ===================== scratch (device globals) =============================
__device__ __align__(128) float g_scores[(size_t)4 * S_ * D_ + 128];
__device__ __align__(128) float g_tmp[(size_t)S_ * D_];
__device__ __align__(128) float g_x1[(size_t)S_ * D_];

__device__ __align__(128) __half g_h[(size_t)S_ * D_];
__device__ __align__(128) __half g_qkv[(size_t)S_ * QKV3];
__device__ __align__(128) __half g_p[(size_t)NH * S_ * S_];      // scores then p
__device__ __align__(128) __half g_vt[(size_t)NH * DH * S_];
__device__ __align__(128) __half g_ctx[(size_t)S_ * D_];
__device__ __align__(128) __half g_m1[(size_t)S_ * DFF];

__device__ __align__(128) __half g_wq[(size_t)QKV3 * D_];
__device__ __align__(128) __half g_wo[(size_t)D_ * D_];
__device__ __align__(128) __half g_w1[(size_t)DFF * D_];
__device__ __align__(128) __half g_w2[(size_t)D_ * DFF];

// ===================== reductions ===========================================
__device__ __forceinline__ float blockReduceSum(float v) {
    __shared__ float red[32];
    __syncthreads();
    int lane = threadIdx.x & 31, w = threadIdx.x >> 5;
    #pragma unroll
    for (int o = 16; o; o >>= 1) v += __shfl_xor_sync(0xffffffffu, v, o);
    if (lane == 0) red[w] = v;
    __syncthreads();
    if (w == 0) {
        float r = (lane < ((blockDim.x + 31) >> 5)) ? red[lane] : 0.f;
        #pragma unroll
        for (int o = 16; o; o >>= 1) r += __shfl_xor_sync(0xffffffffu, r, o);
        if (lane == 0) red[0] = r;
    }
    __syncthreads();
    return red[0];
}
__device__ __forceinline__ float blockReduceMax(float v) {
    __shared__ float red[32];
    __syncthreads();
    int lane = threadIdx.x & 31, w = threadIdx.x >> 5;
    #pragma unroll
    for (int o = 16; o; o >>= 1) v = fmaxf(v, __shfl_xor_sync(0xffffffffu, v, o));
    if (lane == 0) red[w] = v;
    __syncthreads();
    if (w == 0) {
        float r = (lane < ((blockDim.x + 31) >> 5)) ? red[lane] : -3.0e38f;
        #pragma unroll
        for (int o = 16; o; o >>= 1) r = fmaxf(r, __shfl_xor_sync(0xffffffffu, r, o));
        if (lane == 0) red[0] = r;
    }
    __syncthreads();
    return red[0];
}

// ===================== LayerNorm ============================================
template<bool TOF16>
__global__ void __launch_bounds__(256) ln_kernel(
    const float* __restrict__ in, const float* __restrict__ gam,
    const float* __restrict__ bet, const float* __restrict__ res,
    float* __restrict__ outf, __half* __restrict__ oh)
{
    const int row = blockIdx.x;
    const float* x = in + (size_t)row * D_;
    __shared__ float sm[D_];
    float s = 0.f;
    for (int j = threadIdx.x; j < D_; j += blockDim.x) {
        float v = x[j]; sm[j] = v; s += v;
    }
    const float mu = blockReduceSum(s) * (1.0f / D_);
    float sq = 0.f;
    for (int j = threadIdx.x; j < D_; j += blockDim.x) {
        float d = sm[j] - mu; sq += d * d;
    }
    const float var = blockReduceSum(sq) * (1.0f / D_);
    const float inv = rsqrtf(var + 1e-5f);
    for (int j = threadIdx.x; j < D_; j += blockDim.x) {
        float v = (sm[j] - mu) * inv * gam[j] + bet[j];
        if (TOF16) {
            oh[(size_t)row * D_ + j] = __float2half_rn(v);
        } else {
            if (res) v += res[(size_t)row * D_ + j];
            outf[(size_t)row * D_ + j] = v;
        }
    }
}

// ===================== fused: x1 = x + LN(a), ho = LN(x1) -> fp16 ==========
__global__ void __launch_bounds__(256) ln_res_ln_kernel(
    const float* __restrict__ a, const float* __restrict__ g1,
    const float* __restrict__ b1, const float* __restrict__ x,
    const float* __restrict__ g2, const float* __restrict__ b2,
    float* __restrict__ x1_out, __half* __restrict__ ho)
{
    const int row = blockIdx.x;
    const float* ar = a + (size_t)row * D_;
    __shared__ float sm[D_];
    float s = 0.f;
    for (int j = threadIdx.x; j < D_; j += blockDim.x) {
        float v = ar[j]; sm[j] = v; s += v;
    }
    float mu = blockReduceSum(s) * (1.0f / D_);
    float sq = 0.f;
    for (int j = threadIdx.x; j < D_; j += blockDim.x) {
        float d = sm[j] - mu; sq += d * d;
    }
    float var = blockReduceSum(sq) * (1.0f / D_);
    float inv = rsqrtf(var + 1e-5f);
    float s2 = 0.f;
    for (int j = threadIdx.x; j < D_; j += blockDim.x) {
        float v = (sm[j] - mu) * inv * g1[j] + b1[j] + x[(size_t)row * D_ + j];
        sm[j] = v;
        x1_out[(size_t)row * D_ + j] = v;
        s2 += v;
    }
    mu = blockReduceSum(s2) * (1.0f / D_);
    sq = 0.f;
    for (int j = threadIdx.x; j < D_; j += blockDim.x) {
        float d = sm[j] - mu; sq += d * d;
    }
    var = blockReduceSum(sq) * (1.0f / D_);
    inv = rsqrtf(var + 1e-5f);
    for (int j = threadIdx.x; j < D_; j += blockDim.x)
        ho[(size_t)row * D_ + j] =
            __float2half_rn((sm[j] - mu) * inv * g2[j] + b2[j]);
}

// ===================== causal softmax (in place, fp16) ======================
__global__ void __launch_bounds__(256) softmax_kernel(int h0)
{
    const int i = blockIdx.x;
    const int h = blockIdx.y + h0;
    const size_t base = ((size_t)h * S_ + i) * S_;
    __half* ph = g_p + base;
    const int n = i + 1;
    const int fill_end = ((i >> 7) + 1) << 7;   // next multiple of 128
    __shared__ float sm[S_];
    float m = -3.0e38f;
    for (int j = threadIdx.x; j < n; j += blockDim.x) {
        float v = __half2float(ph[j]); sm[j] = v; m = fmaxf(m, v);
    }
    m = blockReduceMax(m);
    float s = 0.f;
    for (int j = threadIdx.x; j < n; j += blockDim.x) {
        float e = expf(sm[j] - m); sm[j] = e; s += e;
    }
    const float inv = 1.0f / blockReduceSum(s);
    const __half z = __float2half_rn(0.f);
    for (int j = threadIdx.x; j < n; j += blockDim.x)
        ph[j] = __float2half_rn(sm[j] * inv);
    for (int j = n + threadIdx.x; j < fill_end; j += blockDim.x) ph[j] = z;
}

// ===================== weight convert + transpose ===========================
__global__ void __launch_bounds__(256) convw_kernel(
    const float* __restrict__ W, int K, int N, __half* __restrict__ o)
{
    __shared__ float t[64][33];
    const int n0 = blockIdx.x * 32, k0 = blockIdx.y * 64;
    const int tx = threadIdx.x, ty = threadIdx.y;  // 32 x 8
    #pragma unroll
    for (int j = 0; j < 8; j++)
        t[ty + j * 8][tx] = W[(size_t)(k0 + ty + j * 8) * N + n0 + tx];
    __syncthreads();
    #pragma unroll
    for (int j = 0; j < 4; j++) {
        const int n = ty + j * 8;
        __half2 hv = __floats2half2_rn(t[tx * 2][n], t[tx * 2 + 1][n]);
        *(__half2*)(o + (size_t)(n0 + n) * K + k0 + tx * 2) = hv;
    }
}

// ===================== V transpose (fp16) ===================================
__global__ void __launch_bounds__(256) vtrans_kernel()
{
    __shared__ __half th[32][33];
    const int h = blockIdx.z;
    const int s0 = blockIdx.x * 32, d0 = blockIdx.y * 32;
    const int tx = threadIdx.x, ty = threadIdx.y;
    #pragma unroll
    for (int j = 0; j < 4; j++)
        th[ty + j * 8][tx] =
            g_qkv[(size_t)(s0 + ty + j * 8) * QKV3 + 2 * D_ + h * DH + d0 + tx];
    __syncthreads();
    #pragma unroll
    for (int j = 0; j < 4; j++)
        g_vt[((size_t)h * DH + d0 + ty + j * 8) * S_ + s0 + tx] = th[tx][ty + j * 8];
}

// ===================== P@V partial combine (column half) ====================
// Processes columns [c0, c0+1024) of all rows. nb(row) = (row>>9)+1 buffers.
__global__ void __launch_bounds__(256) combine_pv_kernel(int c0)
{
    const size_t lin = ((size_t)blockIdx.x * 256 + threadIdx.x) * 4;
    const int r = (int)(lin >> 10);          // row = lin / 1024
    const int c = (int)(lin & 1023);
    const size_t idx = (size_t)r * D_ + c0 + c;
    const int nb = (r >> 9) + 1;
    float4 s = *(const float4*)(g_scores + idx);
    for (int b = 1; b < nb; b++) {
        const float4 p = *(const float4*)(g_scores + (size_t)b * S_ * D_ + idx);
        s.x += p.x; s.y += p.y; s.z += p.z; s.w += p.w;
    }
    __half2 h0 = __floats2half2_rn(s.x, s.y);
    __half2 h1 = __floats2half2_rn(s.z, s.w);
    *(__half2*)(g_ctx + idx)     = h0;
    *(__half2*)(g_ctx + idx + 2) = h1;
}

// ===================== fp16 tensor-core GEMM (mma.sync) =====================
// C[M,N] = A[M,K] @ B[N,K]^T, fp16 in, fp32 accumulate.
// CTA: 128x128 tile, 256 thr (8 warps, 2x4 grid, 64x32/warp), BK=64
// (4 k16 steps per stage), 3-stage cp.async pipeline, 2 CTAs/SM.
// EPI: 0=+bias, 1=+bias+gelu, 2=*scale, 3=none.  OUTF16: emit fp16.
// KSPLIT>0: bx = K-slice index (width KSPLIT); output fp32 partial buffer bx.
#define PITCHB 144                 // smem row pitch in bytes (64 fp16 + 16B pad)
#define ABYTES (128 * PITCHB)      // 18432 B per tile (A or B)
#define STAGEB (2 * ABYTES)        // 36864 B per stage
#define NSTAGE 3

template<int EPI, bool OUTF16, bool CSKIP, bool KLIM, int KSPLIT>
__global__ void __launch_bounds__(256, 2) gemm_mma(
    const __half* __restrict__ A, int lda, size_t astride,
    const __half* __restrict__ B, int ldb, size_t bstride,
    const float* __restrict__ bias,
    float* __restrict__ Cf, __half* __restrict__ Ch,
    int ldc, size_t cstride,
    int K, float scale)
{
    const int bx = blockIdx.x, by = blockIdx.y, bz = blockIdx.z;
    const int nblk = KSPLIT ? 0 : bx;          // N-tile index
    if (CSKIP && nblk > by) return;
    A += (size_t)bz * astride;
    B += (size_t)bz * bstride;
    if (OUTF16) Ch += (size_t)bz * cstride;
    else        Cf += (size_t)bz * cstride;

    int kend = K;
    if (KLIM) { int kl = (by + 1) * 128; if (kl < kend) kend = kl; }
    int kbeg = 0;
    if (KSPLIT) {
        kbeg = bx * KSPLIT;
        if (kbeg >= kend) return;
        if (kend > kbeg + KSPLIT) kend = kbeg + KSPLIT;
        Cf += (size_t)bx * ((size_t)S_ * D_);  // partial buffer bx
    }
    const int NC = (kend - kbeg) >> 6;   // chunks of 64

    extern __shared__ char smem[];
    const uint32_t sbase = smem_to_u32(smem);
    const int tid = threadIdx.x;
    const int lane = tid & 31, wid = tid >> 5;
    const int wm = wid & 1, wn = wid >> 1;   // 2 x 4 warp grid

    const __half* arow = A + (size_t)(by * 128) * lda + kbeg;
    const __half* brow = B + (size_t)(nblk * 128) * ldb + kbeg;

    auto load_chunk = [&](int c) {
        const uint32_t sb = sbase + (uint32_t)(c % NSTAGE) * STAGEB;
        const int k0 = c << 6;
        #pragma unroll
        for (int t = 0; t < 4; t++) {            // A+B: 1024 16B segs each
            const int idx = tid + t * 256;       // 0..1023
            const int r = idx >> 3, seg = idx & 7;
            const uint32_t d = sb + (uint32_t)(r * PITCHB + seg * 16);
            cpa16(d,          arow + (size_t)r * lda + k0 + seg * 8);
            cpa16(d + ABYTES, brow + (size_t)r * ldb + k0 + seg * 8);
        }
        asm volatile("cp.async.commit_group;" ::: "memory");
    };

    float acc[4][4][4];
    #pragma unroll
    for (int i = 0; i < 4; i++)
        #pragma unroll
        for (int j = 0; j < 4; j++)
            #pragma unroll
            for (int q = 0; q < 4; q++) acc[i][j][q] = 0.f;

    load_chunk(0);
    if (NC > 1) load_chunk(1);
    if (NC > 2) load_chunk(2);

    const int lsel = lane & 15;
    const uint32_t a_base = (uint32_t)((wm * 64 + (lane & 15)) * PITCHB + (lane >> 4) * 16);
    const uint32_t b_base = (uint32_t)(ABYTES + (wn * 32 + (lsel & 7)) * PITCHB + (lsel >> 3) * 16);

    for (int c = 0; c < NC; c++) {
        const int rem = NC - 1 - c;   // groups committed after c
        if (rem >= 2)      asm volatile("cp.async.wait_group 2;" ::: "memory");
        else if (rem == 1) asm volatile("cp.async.wait_group 1;" ::: "memory");
        else               asm volatile("cp.async.wait_group 0;" ::: "memory");
        __syncthreads();

        const uint32_t sb = sbase + (uint32_t)(c % NSTAGE) * STAGEB;
        #pragma unroll
        for (int k16 = 0; k16 < 4; k16++) {
            const uint32_t kb = (uint32_t)(k16 * 32);
            uint32_t bf[4][2];
            #pragma unroll
            for (int nt = 0; nt < 4; nt++)
                ldsm_x2(bf[nt][0], bf[nt][1],
                        sb + b_base + (uint32_t)(nt * 8 * PITCHB) + kb);
            #pragma unroll
            for (int mt = 0; mt < 4; mt++) {
                uint32_t af[4];
                ldsm_x4(af[0], af[1], af[2], af[3],
                        sb + a_base + (uint32_t)(mt * 16 * PITCHB) + kb);
                #pragma unroll
                for (int nt = 0; nt < 4; nt++)
                    mma_f16(acc[mt][nt], af, bf[nt]);
            }
        }
        __syncthreads();           // all warps done with stage (c % NSTAGE)
        if (c + 3 < NC) load_chunk(c + 3);
    }

    // -------- epilogue --------------------------------------------------------
    const int r_in = wm * 64 + (lane >> 2);
    const int c_in = wn * 32 + (lane & 3) * 2;
    #pragma unroll
    for (int mt = 0; mt < 4; mt++) {
        #pragma unroll
        for (int half = 0; half < 2; half++) {
            const int grow = by * 128 + r_in + mt * 16 + half * 8;
            #pragma unroll
            for (int nt = 0; nt < 4; nt++) {
                const int gcol = nblk * 128 + c_in + nt * 8;
                float v0 = acc[mt][nt][half * 2 + 0];
                float v1 = acc[mt][nt][half * 2 + 1];
                if (EPI == 0) {
                    v0 += bias[gcol]; v1 += bias[gcol + 1];
                } else if (EPI == 1) {
                    v0 += bias[gcol]; v1 += bias[gcol + 1];
                    const float cst = 0.7978845608028654f;
                    float t0 = tanhf(cst * (v0 + 0.044715f * v0 * v0 * v0));
                    float t1 = tanhf(cst * (v1 + 0.044715f * v1 * v1 * v1));
                    v0 = 0.5f * v0 * (1.0f + t0);
                    v1 = 0.5f * v1 * (1.0f + t1);
                } else if (EPI == 2) {
                    v0 *= scale; v1 *= scale;
                }
                if (OUTF16) {
                    *(__half2*)(Ch + (size_t)grow * ldc + gcol) =
                        __floats2half2_rn(v0, v1);
                } else {
                    float2 f; f.x = v0; f.y = v1;
                    *(float2*)(Cf + (size_t)grow * ldc + gcol) = f;
                }
            }
        }
    }
}

// ===================== driver ===============================================
extern "C" void kernel_launch(void* const* d_in, const int* in_sizes, int n_in,
                              void* d_out, int out_size)
{
    (void)in_sizes; (void)n_in; (void)out_size;
    const float* x        = (const float*)d_in[0];
    const float* Wqkv     = (const float*)d_in[2];
    const float* bqkv     = (const float*)d_in[3];
    const float* Wo       = (const float*)d_in[4];
    const float* bo       = (const float*)d_in[5];
    const float* W1       = (const float*)d_in[6];
    const float* b1       = (const float*)d_in[7];
    const float* W2       = (const float*)d_in[8];
    const float* b2       = (const float*)d_in[9];
    const float* g_ln_in  = (const float*)d_in[10];
    const float* b_ln_in  = (const float*)d_in[11];
    const float* g_s1     = (const float*)d_in[12];
    const float* b_s1     = (const float*)d_in[13];
    const float* g_ln_out = (const float*)d_in[14];
    const float* b_ln_out = (const float*)d_in[15];
    const float* g_s2     = (const float*)d_in[16];
    const float* b_s2     = (const float*)d_in[17];
    float* out = (float*)d_out;

    float *psc, *ptmp, *px1;
    __half *ph, *pq, *pp, *pv, *pc, *pm, *wq, *wo, *w1, *w2;
    cudaGetSymbolAddress((void**)&psc, g_scores);
    cudaGetSymbolAddress((void**)&ptmp, g_tmp);
    cudaGetSymbolAddress((void**)&px1, g_x1);
    cudaGetSymbolAddress((void**)&ph, g_h);
    cudaGetSymbolAddress((void**)&pq, g_qkv);
    cudaGetSymbolAddress((void**)&pp, g_p);
    cudaGetSymbolAddress((void**)&pv, g_vt);
    cudaGetSymbolAddress((void**)&pc, g_ctx);
    cudaGetSymbolAddress((void**)&pm, g_m1);
    cudaGetSymbolAddress((void**)&wq, g_wq);
    cudaGetSymbolAddress((void**)&wo, g_wo);
    cudaGetSymbolAddress((void**)&w1, g_w1);
    cudaGetSymbolAddress((void**)&w2, g_w2);

    const int SMEM = NSTAGE * STAGEB;  // 110592
    cudaFuncSetAttribute(gemm_mma<0, true , false, false, 0>,
                         cudaFuncAttributeMaxDynamicSharedMemorySize, SMEM);
    cudaFuncSetAttribute(gemm_mma<2, true , true , false, 0>,
                         cudaFuncAttributeMaxDynamicSharedMemorySize, SMEM);
    cudaFuncSetAttribute(gemm_mma<3, false, false, true , 512>,
                         cudaFuncAttributeMaxDynamicSharedMemorySize, SMEM);
    cudaFuncSetAttribute(gemm_mma<0, false, false, false, 0>,
                         cudaFuncAttributeMaxDynamicSharedMemorySize, SMEM);
    cudaFuncSetAttribute(gemm_mma<1, true , false, false, 0>,
                         cudaFuncAttributeMaxDynamicSharedMemorySize, SMEM);

    // Side stream + events (capture-time only; no device memory involved).
    cudaStream_t s2;
    cudaStreamCreateWithFlags(&s2, cudaStreamNonBlocking);
    cudaEvent_t eFork, eLN, eQKV, eScL, eScH, eSmL, eSmH, ePvL, eCmbL;
    cudaEventCreateWithFlags(&eFork, cudaEventDisableTiming);
    cudaEventCreateWithFlags(&eLN  , cudaEventDisableTiming);
    cudaEventCreateWithFlags(&eQKV , cudaEventDisableTiming);
    cudaEventCreateWithFlags(&eScL , cudaEventDisableTiming);
    cudaEventCreateWithFlags(&eScH , cudaEventDisableTiming);
    cudaEventCreateWithFlags(&eSmL , cudaEventDisableTiming);
    cudaEventCreateWithFlags(&eSmH , cudaEventDisableTiming);
    cudaEventCreateWithFlags(&ePvL , cudaEventDisableTiming);
    cudaEventCreateWithFlags(&eCmbL, cudaEventDisableTiming);

    const dim3 cvblk(32, 8);
    const float iscale = 0.08838834764831845f;

    // ---- prologue: convw(Wqkv) on main, ln on s2 (parallel) -----------------
    cudaEventRecord(eFork, 0);
    cudaStreamWaitEvent(s2, eFork, 0);
    convw_kernel<<<dim3(QKV3 / 32, D_ / 64), cvblk>>>(Wqkv, D_, QKV3, wq);   // 1
    ln_kernel<true><<<S_, 256, 0, s2>>>(x, g_ln_in, b_ln_in,
                                        nullptr, nullptr, ph);               // 2
    cudaEventRecord(eLN, s2);
    convw_kernel<<<dim3(D_ / 32, D_ / 64), cvblk, 0, s2>>>(Wo, D_, D_, wo);  // 3
    cudaStreamWaitEvent(0, eLN, 0);
    // ---- main: QKV GEMM  <-- profiled launch #4 -----------------------------
    gemm_mma<0, true, false, false, 0><<<dim3(QKV3 / 128, S_ / 128, 1), 256, SMEM>>>(
        ph, D_, 0, wq, D_, 0, bqkv, nullptr, pq, QKV3, 0, D_, 0.f);          // 4
    cudaEventRecord(eQKV, 0);
    convw_kernel<<<dim3(DFF / 32, D_ / 64), cvblk, 0, s2>>>(W1, D_, DFF, w1);// 5
    convw_kernel<<<dim3(D_ / 32, DFF / 64), cvblk, 0, s2>>>(W2, DFF, D_, w2);// 6
    cudaStreamWaitEvent(s2, eQKV, 0);
    vtrans_kernel<<<dim3(S_ / 32, DH / 32, NH), cvblk, 0, s2>>>();           // 7
    // ---- main: scores in two head-halves ------------------------------------
    gemm_mma<2, true, true, false, 0><<<dim3(S_ / 128, S_ / 128, 8), 256, SMEM>>>(
        pq, QKV3, (size_t)DH, pq + D_, QKV3, (size_t)DH,
        nullptr, nullptr, pp, S_, (size_t)S_ * S_, DH, iscale);              // 8
    cudaEventRecord(eScL, 0);
    gemm_mma<2, true, true, false, 0><<<dim3(S_ / 128, S_ / 128, 8), 256, SMEM>>>(
        pq + 8 * DH, QKV3, (size_t)DH, pq + D_ + 8 * DH, QKV3, (size_t)DH,
        nullptr, nullptr, pp + (size_t)8 * S_ * S_, S_, (size_t)S_ * S_,
        DH, iscale);                                                         // 9
    cudaEventRecord(eScH, 0);
    // ---- s2: softmax halves overlap scores_hi / P@V_lo ----------------------
    cudaStreamWaitEvent(s2, eScL, 0);
    softmax_kernel<<<dim3(S_, 8), 256, 0, s2>>>(0);                          // 10
    cudaEventRecord(eSmL, s2);
    cudaStreamWaitEvent(s2, eScH, 0);
    softmax_kernel<<<dim3(S_, 8), 256, 0, s2>>>(8);                          // 11
    cudaEventRecord(eSmH, s2);
    // ---- main: P@V halves ---------------------------------------------------
    cudaStreamWaitEvent(0, eSmL, 0);
    gemm_mma<3, false, false, true, 512><<<dim3(4, S_ / 128, 8), 256, SMEM>>>(
        pp, S_, (size_t)S_ * S_, pv, S_, (size_t)DH * S_,
        nullptr, psc, nullptr, D_, (size_t)DH, S_, 0.f);                     // 12
    cudaEventRecord(ePvL, 0);
    cudaStreamWaitEvent(0, eSmH, 0);
    gemm_mma<3, false, false, true, 512><<<dim3(4, S_ / 128, 8), 256, SMEM>>>(
        pp + (size_t)8 * S_ * S_, S_, (size_t)S_ * S_,
        pv + (size_t)8 * DH * S_, S_, (size_t)DH * S_,
        nullptr, psc + 8 * DH, nullptr, D_, (size_t)DH, S_, 0.f);            // 13
    // ---- combine: low cols on s2 (overlaps P@V high), high cols on main -----
    cudaStreamWaitEvent(s2, ePvL, 0);
    combine_pv_kernel<<<(S_ * 1024) / (256 * 4), 256, 0, s2>>>(0);           // 14
    cudaEventRecord(eCmbL, s2);
    combine_pv_kernel<<<(S_ * 1024) / (256 * 4), 256>>>(1024);               // 15
    cudaStreamWaitEvent(0, eCmbL, 0);
    // ---- tail ---------------------------------------------------------------
    gemm_mma<0, false, false, false, 0><<<dim3(D_ / 128, S_ / 128, 1), 256, SMEM>>>(
        pc, D_, 0, wo, D_, 0, bo, ptmp, nullptr, D_, 0, D_, 0.f);            // 16
    ln_res_ln_kernel<<<S_, 256>>>(ptmp, g_s1, b_s1, x, g_ln_out, b_ln_out,
                                  px1, ph);                                  // 17
    gemm_mma<1, true, false, false, 0><<<dim3(DFF / 128, S_ / 128, 1), 256, SMEM>>>(
        ph, D_, 0, w1, D_, 0, b1, nullptr, pm, DFF, 0, D_, 0.f);             // 18
    gemm_mma<0, false, false, false, 0><<<dim3(D_ / 128, S_ / 128, 1), 256, SMEM>>>(
        pm, DFF, 0, w2, DFF, 0, b2, ptmp, nullptr, D_, 0, DFF, 0.f);         // 19
    ln_kernel<false><<<S_, 256>>>(ptmp, g_s2, b_s2, px1, out, nullptr);      // 20
}